// round 1
// baseline (speedup 1.0000x reference)
#include <cuda_runtime.h>
#include <cstdint>

#define B_ 32
#define S_ 196
#define T_ 64
#define H_ 1024
#define V_ 32000
#define G4 4096      // 4*H
#define NQG 5120     // H (attn) + 4H (W_hh)
#define MROWS 2048   // B*T
#define SPLITK 4

// ---------------- device scratch (no allocations allowed) ----------------
__device__ float g_Emb[MROWS * H_];          // gathered embeddings, rows m = t*B+b
__device__ float g_EG[(size_t)MROWS * G4];   // emb @ W_ih_embT + b_ih + b_hh
__device__ float g_qg[SPLITK * B_ * NQG];    // split-K partials: [q | h@W_hhT]
__device__ float g_gc[SPLITK * B_ * G4];     // split-K partials: ctx @ W_ihcT
__device__ float g_ctx[B_ * H_];
__device__ float g_h[B_ * H_];
__device__ float g_c[B_ * H_];
__device__ float g_hall[MROWS * H_];         // h_t for deferred vocab GEMM

// ---------------- helpers ----------------
__device__ __forceinline__ float rtf(float x) {
    unsigned r;
    asm("cvt.rna.tf32.f32 %0, %1;" : "=r"(r) : "f"(x));
    return __uint_as_float(r);
}

__device__ __forceinline__ void mma_tf32(float* d, const unsigned* a, const unsigned* b) {
    asm volatile(
        "mma.sync.aligned.m16n8k8.row.col.f32.tf32.tf32.f32 "
        "{%0,%1,%2,%3}, {%4,%5,%6,%7}, {%8,%9}, {%0,%1,%2,%3};"
        : "+f"(d[0]), "+f"(d[1]), "+f"(d[2]), "+f"(d[3])
        : "r"(a[0]), "r"(a[1]), "r"(a[2]), "r"(a[3]), "r"(b[0]), "r"(b[1]));
}

// ---------------- generic tf32 GEMM: C[M,N] = A[M,K] @ B[N,K]^T ----------------
// B operand may be split row-wise across two tensors (B0 rows [0,nsplit), B1 rest).
// mode 0: out[row*N+col] = acc + bias0[col] + bias1[col]
// mode 1: out[z*M*N + row*N + col] = acc            (split-K partials)
// mode 2: out[(row&31)*T*V + (row>>5)*V + col] = acc + bias0[col]  (logits scatter)
#define BM 32
#define BN 64
#define BK 32

__global__ void __launch_bounds__(128)
gemm_tf32(const float* __restrict__ A, int lda,
          const float* __restrict__ B0, int ldb0, int nsplit,
          const float* __restrict__ B1, int ldb1,
          float* __restrict__ out, int M, int N, int Kchunk,
          const float* __restrict__ bias0, const float* __restrict__ bias1,
          int mode)
{
    __shared__ float As[BM][BK + 1];
    __shared__ float Bs[BN][BK + 1];

    const int tid  = threadIdx.x;
    const int warp = tid >> 5;
    const int lane = tid & 31;
    const int gid  = lane >> 2;   // 0..7
    const int tig  = lane & 3;    // 0..3
    const int bn0  = blockIdx.x * BN;
    const int bm0  = blockIdx.y * BM;
    const int kb   = blockIdx.z * Kchunk;

    float acc[2][2][4];
#pragma unroll
    for (int i = 0; i < 2; i++)
#pragma unroll
        for (int j = 0; j < 2; j++)
#pragma unroll
            for (int q = 0; q < 4; q++) acc[i][j][q] = 0.f;

    for (int kc = 0; kc < Kchunk; kc += BK) {
        const int k0 = kb + kc;
        // load A tile (32x32 = 256 float4, 2 per thread)
#pragma unroll
        for (int i = 0; i < 2; i++) {
            int idx4 = tid + i * 128;
            int r = idx4 >> 3, c4 = (idx4 & 7) << 2;
            float4 v = *reinterpret_cast<const float4*>(A + (size_t)(bm0 + r) * lda + k0 + c4);
            As[r][c4 + 0] = rtf(v.x); As[r][c4 + 1] = rtf(v.y);
            As[r][c4 + 2] = rtf(v.z); As[r][c4 + 3] = rtf(v.w);
        }
        // load B tile (64x32 = 512 float4, 4 per thread)
#pragma unroll
        for (int i = 0; i < 4; i++) {
            int idx4 = tid + i * 128;
            int r = idx4 >> 3, c4 = (idx4 & 7) << 2;
            int ng = bn0 + r;
            const float* bp = (ng < nsplit) ? (B0 + (size_t)ng * ldb0)
                                            : (B1 + (size_t)(ng - nsplit) * ldb1);
            float4 v = *reinterpret_cast<const float4*>(bp + k0 + c4);
            Bs[r][c4 + 0] = rtf(v.x); Bs[r][c4 + 1] = rtf(v.y);
            Bs[r][c4 + 2] = rtf(v.z); Bs[r][c4 + 3] = rtf(v.w);
        }
        __syncthreads();

        const int wn = warp * 16;
#pragma unroll
        for (int k8 = 0; k8 < 4; k8++) {
            const int kk = k8 * 8;
            unsigned a[2][4], b[2][2];
#pragma unroll
            for (int mi = 0; mi < 2; mi++) {
                int mr = mi * 16 + gid;
                a[mi][0] = __float_as_uint(As[mr][kk + tig]);
                a[mi][1] = __float_as_uint(As[mr + 8][kk + tig]);
                a[mi][2] = __float_as_uint(As[mr][kk + tig + 4]);
                a[mi][3] = __float_as_uint(As[mr + 8][kk + tig + 4]);
            }
#pragma unroll
            for (int nj = 0; nj < 2; nj++) {
                int nr = wn + nj * 8 + gid;
                b[nj][0] = __float_as_uint(Bs[nr][kk + tig]);
                b[nj][1] = __float_as_uint(Bs[nr][kk + tig + 4]);
            }
#pragma unroll
            for (int mi = 0; mi < 2; mi++)
#pragma unroll
                for (int nj = 0; nj < 2; nj++)
                    mma_tf32(acc[mi][nj], a[mi], b[nj]);
        }
        __syncthreads();
    }

    // epilogue
    const int wn = warp * 16;
#pragma unroll
    for (int mi = 0; mi < 2; mi++) {
#pragma unroll
        for (int nj = 0; nj < 2; nj++) {
#pragma unroll
            for (int hrow = 0; hrow < 2; hrow++) {
                int row = bm0 + mi * 16 + gid + hrow * 8;
                int cg  = bn0 + wn + nj * 8 + tig * 2;
                float v0 = acc[mi][nj][hrow * 2 + 0];
                float v1 = acc[mi][nj][hrow * 2 + 1];
                if (mode == 0) {
                    size_t o = (size_t)row * N + cg;
                    out[o]     = v0 + bias0[cg]     + bias1[cg];
                    out[o + 1] = v1 + bias0[cg + 1] + bias1[cg + 1];
                } else if (mode == 1) {
                    size_t o = (size_t)blockIdx.z * M * N + (size_t)row * N + cg;
                    out[o] = v0; out[o + 1] = v1;
                } else {
                    int bb = row & 31, tt = row >> 5;
                    size_t o = (size_t)bb * T_ * V_ + (size_t)tt * V_ + cg;
                    out[o]     = v0 + bias0[cg];
                    out[o + 1] = v1 + bias0[cg + 1];
                }
            }
        }
    }
}

// ---------------- setup kernels ----------------
__global__ void zero_hc() {
    int i = blockIdx.x * 256 + threadIdx.x;   // 32768 total
    g_h[i] = 0.f; g_c[i] = 0.f;
}

__global__ void gather_emb(const int* __restrict__ captions, const float* __restrict__ table) {
    int m = blockIdx.x;               // 0..2047, m = t*B + b
    int b = m & 31, t = m >> 5;
    int tok = captions[b * T_ + t];
    const float4* src = reinterpret_cast<const float4*>(table + (size_t)tok * H_);
    float4* dst = reinterpret_cast<float4*>(g_Emb + (size_t)m * H_);
    dst[threadIdx.x] = src[threadIdx.x];   // 256 threads * float4 = 1024 floats
}

// ---------------- fused attention: scores -> softmax -> ctx (fp32) ----------------
__global__ void __launch_bounds__(256) attn_kernel(const float* __restrict__ memory) {
    const int b = blockIdx.x, tid = threadIdx.x;
    const int warp = tid >> 5, lane = tid & 31;
    __shared__ float q[H_];
    __shared__ float sc[S_];
    __shared__ float red[256];
    const float* mb = memory + (size_t)b * S_ * H_;

    // q = sum of split-K partials (first H cols of qg)
    for (int k = tid; k < H_; k += 256) {
        float v = 0.f;
#pragma unroll
        for (int z = 0; z < SPLITK; z++) v += g_qg[z * B_ * NQG + b * NQG + k];
        q[k] = v;
    }
    __syncthreads();

    // scores: one warp per s
    for (int s = warp; s < S_; s += 8) {
        const float* row = mb + (size_t)s * H_;
        float a = 0.f;
#pragma unroll 8
        for (int k = lane; k < H_; k += 32) a += q[k] * row[k];
#pragma unroll
        for (int o = 16; o; o >>= 1) a += __shfl_xor_sync(0xffffffffu, a, o);
        if (lane == 0) sc[s] = a;
    }
    __syncthreads();

    // softmax over S=196
    float v = (tid < S_) ? sc[tid] : -3.4e38f;
    red[tid] = v; __syncthreads();
    for (int o = 128; o; o >>= 1) { if (tid < o) red[tid] = fmaxf(red[tid], red[tid + o]); __syncthreads(); }
    float mx = red[0]; __syncthreads();
    float e = (tid < S_) ? expf(v - mx) : 0.f;
    red[tid] = e; __syncthreads();
    for (int o = 128; o; o >>= 1) { if (tid < o) red[tid] += red[tid + o]; __syncthreads(); }
    float inv = 1.f / red[0];
    if (tid < S_) sc[tid] = e * inv;
    __syncthreads();

    // ctx: each thread owns 4 h-positions (coalesced)
    float acc[4] = {0.f, 0.f, 0.f, 0.f};
    for (int s = 0; s < S_; s++) {
        float w = sc[s];
        const float* row = mb + (size_t)s * H_;
#pragma unroll
        for (int j = 0; j < 4; j++) acc[j] += w * row[tid + j * 256];
    }
#pragma unroll
    for (int j = 0; j < 4; j++) g_ctx[b * H_ + tid + j * 256] = acc[j];
}

// ---------------- LSTM cell: sum partials, activations, state update ----------------
__global__ void __launch_bounds__(256) cell_kernel(int t) {
    int idx = blockIdx.x * 256 + threadIdx.x;   // 0..32767 = b*1024+j
    int b = idx >> 10, j = idx & 1023;
    const float* eg = g_EG + (size_t)(t * B_ + b) * G4;
    float gate[4];
#pragma unroll
    for (int gi = 0; gi < 4; gi++) {
        int n = j + gi * H_;
        float v = eg[n];
#pragma unroll
        for (int z = 0; z < SPLITK; z++) {
            v += g_gc[z * B_ * G4 + b * G4 + n];
            v += g_qg[z * B_ * NQG + b * NQG + H_ + n];
        }
        gate[gi] = v;
    }
    float ig = 1.f / (1.f + expf(-gate[0]));
    float fg = 1.f / (1.f + expf(-gate[1]));
    float gg = tanhf(gate[2]);
    float og = 1.f / (1.f + expf(-gate[3]));
    float c = fg * g_c[idx] + ig * gg;
    float h = og * tanhf(c);
    g_c[idx] = c;
    g_h[idx] = h;
    g_hall[(size_t)(t * B_ + b) * H_ + j] = h;
}

__global__ void final_copy(float* __restrict__ out, int out_size) {
    int i = blockIdx.x * 256 + threadIdx.x;     // 32768
    size_t base = (size_t)B_ * T_ * V_;
    if ((size_t)out_size >= base + 2u * B_ * H_) {
        out[base + i]         = g_h[i];
        out[base + 32768 + i] = g_c[i];
    }
}

// ---------------- launch ----------------
extern "C" void kernel_launch(void* const* d_in, const int* in_sizes, int n_in,
                              void* d_out, int out_size) {
    const float* memory    = (const float*)d_in[0];
    const int*   captions  = (const int*)  d_in[1];
    const float* emb_table = (const float*)d_in[2];
    const float* attn_W    = (const float*)d_in[3];
    const float* W_ih      = (const float*)d_in[4];
    const float* W_hh      = (const float*)d_in[5];
    const float* b_ih      = (const float*)d_in[6];
    const float* b_hh      = (const float*)d_in[7];
    const float* W_out     = (const float*)d_in[8];
    const float* b_out     = (const float*)d_in[9];
    float* out = (float*)d_out;

    float *pEmb, *pEG, *pqg, *pgc, *pctx, *ph, *phall;
    cudaGetSymbolAddress((void**)&pEmb,  g_Emb);
    cudaGetSymbolAddress((void**)&pEG,   g_EG);
    cudaGetSymbolAddress((void**)&pqg,   g_qg);
    cudaGetSymbolAddress((void**)&pgc,   g_gc);
    cudaGetSymbolAddress((void**)&pctx,  g_ctx);
    cudaGetSymbolAddress((void**)&ph,    g_h);
    cudaGetSymbolAddress((void**)&phall, g_hall);

    zero_hc<<<128, 256>>>();
    gather_emb<<<MROWS, 256>>>(captions, emb_table);

    // EG = Emb @ W_ih[:, :H]^T + b_ih + b_hh   (batched over all t)
    gemm_tf32<<<dim3(G4 / BN, MROWS / BM, 1), 128>>>(
        pEmb, H_, W_ih, 2 * H_, G4, nullptr, 0,
        pEG, MROWS, G4, H_, b_ih, b_hh, 0);

    for (int t = 0; t < T_; t++) {
        // qg = h @ [attn_W ; W_hh]^T  (split-K partials)
        gemm_tf32<<<dim3(NQG / BN, 1, SPLITK), 128>>>(
            ph, H_, attn_W, H_, H_, W_hh, H_,
            pqg, B_, NQG, H_ / SPLITK, nullptr, nullptr, 1);

        attn_kernel<<<B_, 256>>>(memory);

        // gc = ctx @ W_ih[:, H:2H]^T  (split-K partials)
        gemm_tf32<<<dim3(G4 / BN, 1, SPLITK), 128>>>(
            pctx, H_, W_ih + H_, 2 * H_, G4, nullptr, 0,
            pgc, B_, G4, H_ / SPLITK, nullptr, nullptr, 1);

        cell_kernel<<<128, 256>>>(t);
    }

    // deferred vocab projection: logits = h_all @ W_out^T + b_out (scattered to [B,T,V])
    gemm_tf32<<<dim3(V_ / BN, MROWS / BM, 1), 128>>>(
        phall, H_, W_out, H_, V_, nullptr, 0,
        out, MROWS, V_, H_, b_out, nullptr, 2);

    final_copy<<<128, 256>>>(out, out_size);
}

// round 3
// speedup vs baseline: 1.4270x; 1.4270x over previous
#include <cuda_runtime.h>
#include <cstdint>

#define B_ 32
#define S_ 196
#define T_ 64
#define H_ 1024
#define V_ 32000
#define G4 4096      // 4*H
#define MROWS 2048   // B*T
#define SPLITK 8

// ---------------- device scratch (no allocations allowed) ----------------
__device__ float g_Emb[MROWS * H_];                 // gathered embeddings, rows m = t*B+b
__device__ float g_EG[(size_t)MROWS * G4];          // emb @ W_ih_embT + b_ih + b_hh
__device__ float g_P[(size_t)B_ * S_ * H_];         // memory @ attn_W  (scores = h . P)
__device__ float g_qg[SPLITK * B_ * G4];            // split-K partials: h @ W_hhT
__device__ float g_gc[SPLITK * B_ * G4];            // split-K partials: ctx @ W_ihcT
__device__ float g_scores[B_ * S_];
__device__ float g_ctx[B_ * H_];
__device__ float g_h[B_ * H_];
__device__ float g_c[B_ * H_];
__device__ float g_hall[(size_t)MROWS * H_];        // h_t for deferred vocab GEMM

// ---------------- helpers ----------------
__device__ __forceinline__ float rtf(float x) {
    unsigned r;
    asm("cvt.rna.tf32.f32 %0, %1;" : "=r"(r) : "f"(x));
    return __uint_as_float(r);
}

__device__ __forceinline__ void mma_tf32(float* d, const unsigned* a, const unsigned* b) {
    asm volatile(
        "mma.sync.aligned.m16n8k8.row.col.f32.tf32.tf32.f32 "
        "{%0,%1,%2,%3}, {%4,%5,%6,%7}, {%8,%9}, {%0,%1,%2,%3};"
        : "+f"(d[0]), "+f"(d[1]), "+f"(d[2]), "+f"(d[3])
        : "r"(a[0]), "r"(a[1]), "r"(a[2]), "r"(a[3]), "r"(b[0]), "r"(b[1]));
}

// =======================================================================
// Big-tile tf32 GEMM: C[M,N] = A[M,K=1024] @ op(B)^T, 128x128x16 tiles,
// 256 threads, double-buffered smem.
// transB=0: B is [N,K] row-major (ldb = row stride).
// transB=1: B is [K,N] row-major (ldb = row stride) -> effective [N,K].
// mode 0: out[row*N+col] = acc + bias0[col] + bias1[col]
// mode 2: out[(row&31)*T*V + (row>>5)*V + col] = acc + bias0[col]  (logits)
// mode 3: out[row*N+col] = acc
// =======================================================================
#define TM 128
#define TN 128
#define TK 16
#define KTOT 1024
#define NIT (KTOT / TK)

__global__ void __launch_bounds__(256)
gemm_big(const float* __restrict__ A, int lda,
         const float* __restrict__ B, int ldb, int transB,
         float* __restrict__ out, int M, int N,
         const float* __restrict__ bias0, const float* __restrict__ bias1,
         int mode)
{
    __shared__ float As[2][TM][TK + 1];
    __shared__ float Bs[2][TN][TK + 1];

    const int tid  = threadIdx.x;
    const int warp = tid >> 5;
    const int lane = tid & 31;
    const int gid  = lane >> 2;
    const int tig  = lane & 3;
    const int wm   = warp & 3;     // 0..3 -> 32-row slice
    const int wn   = warp >> 2;    // 0..1 -> 64-col slice

    // block swizzle (only used for the 1D logits launch)
    int bx, by;
    {
        int nby = M / TM;
        if (gridDim.y == 1 && nby > 1) {
            const int GW = 10;                 // N/TN must be divisible by GW (250 % 10 == 0)
            int gsz = GW * nby;
            int g = blockIdx.x / gsz, w = blockIdx.x % gsz;
            bx = g * GW + w % GW;
            by = w / GW;
        } else { bx = blockIdx.x; by = blockIdx.y; }
    }
    const int bm0 = by * TM;
    const int bn0 = bx * TN;

    float acc[2][8][4];
#pragma unroll
    for (int i = 0; i < 2; i++)
#pragma unroll
        for (int j = 0; j < 8; j++)
#pragma unroll
            for (int q = 0; q < 4; q++) acc[i][j][q] = 0.f;

    // ---- prologue: load tile 0 into buffer 0 ----
    {
#pragma unroll
        for (int i = 0; i < 2; i++) {
            int idx4 = tid + i * 256;
            int r = idx4 >> 2, c4 = (idx4 & 3) << 2;
            float4 v = *reinterpret_cast<const float4*>(A + (size_t)(bm0 + r) * lda + c4);
            As[0][r][c4 + 0] = rtf(v.x); As[0][r][c4 + 1] = rtf(v.y);
            As[0][r][c4 + 2] = rtf(v.z); As[0][r][c4 + 3] = rtf(v.w);
        }
        if (!transB) {
#pragma unroll
            for (int i = 0; i < 2; i++) {
                int idx4 = tid + i * 256;
                int r = idx4 >> 2, c4 = (idx4 & 3) << 2;
                float4 v = *reinterpret_cast<const float4*>(B + (size_t)(bn0 + r) * ldb + c4);
                Bs[0][r][c4 + 0] = rtf(v.x); Bs[0][r][c4 + 1] = rtf(v.y);
                Bs[0][r][c4 + 2] = rtf(v.z); Bs[0][r][c4 + 3] = rtf(v.w);
            }
        } else {
#pragma unroll
            for (int i = 0; i < 8; i++) {
                int idx = tid + i * 256;
                int r = idx & 127, c = idx >> 7;
                Bs[0][r][c] = rtf(B[(size_t)c * ldb + bn0 + r]);
            }
        }
    }
    __syncthreads();

    int buf = 0;
    for (int kt = 0; kt < NIT; kt++) {
        const bool pre = (kt + 1 < NIT);
        const int k0 = (kt + 1) * TK;
        float4 pa0, pa1, pb0, pb1;
        float pbt[8];
        if (pre) {
            {
                int idx4 = tid;
                int r = idx4 >> 2, c4 = (idx4 & 3) << 2;
                pa0 = *reinterpret_cast<const float4*>(A + (size_t)(bm0 + r) * lda + k0 + c4);
                idx4 = tid + 256; r = idx4 >> 2; c4 = (idx4 & 3) << 2;
                pa1 = *reinterpret_cast<const float4*>(A + (size_t)(bm0 + r) * lda + k0 + c4);
            }
            if (!transB) {
                int idx4 = tid;
                int r = idx4 >> 2, c4 = (idx4 & 3) << 2;
                pb0 = *reinterpret_cast<const float4*>(B + (size_t)(bn0 + r) * ldb + k0 + c4);
                idx4 = tid + 256; r = idx4 >> 2; c4 = (idx4 & 3) << 2;
                pb1 = *reinterpret_cast<const float4*>(B + (size_t)(bn0 + r) * ldb + k0 + c4);
            } else {
#pragma unroll
                for (int i = 0; i < 8; i++) {
                    int idx = tid + i * 256;
                    int r = idx & 127, c = idx >> 7;
                    pbt[i] = B[(size_t)(k0 + c) * ldb + bn0 + r];
                }
            }
        }

        // ---- compute on buffer `buf` ----
#pragma unroll
        for (int k8 = 0; k8 < 2; k8++) {
            const int kk = k8 * 8;
            unsigned a[2][4], b[8][2];
#pragma unroll
            for (int mi = 0; mi < 2; mi++) {
                int mr = wm * 32 + mi * 16 + gid;
                a[mi][0] = __float_as_uint(As[buf][mr][kk + tig]);
                a[mi][1] = __float_as_uint(As[buf][mr + 8][kk + tig]);
                a[mi][2] = __float_as_uint(As[buf][mr][kk + tig + 4]);
                a[mi][3] = __float_as_uint(As[buf][mr + 8][kk + tig + 4]);
            }
#pragma unroll
            for (int nj = 0; nj < 8; nj++) {
                int nr = wn * 64 + nj * 8 + gid;
                b[nj][0] = __float_as_uint(Bs[buf][nr][kk + tig]);
                b[nj][1] = __float_as_uint(Bs[buf][nr][kk + tig + 4]);
            }
#pragma unroll
            for (int mi = 0; mi < 2; mi++)
#pragma unroll
                for (int nj = 0; nj < 8; nj++)
                    mma_tf32(acc[mi][nj], a[mi], b[nj]);
        }

        if (pre) {
            int wb = buf ^ 1;
            {
                int idx4 = tid;
                int r = idx4 >> 2, c4 = (idx4 & 3) << 2;
                As[wb][r][c4 + 0] = rtf(pa0.x); As[wb][r][c4 + 1] = rtf(pa0.y);
                As[wb][r][c4 + 2] = rtf(pa0.z); As[wb][r][c4 + 3] = rtf(pa0.w);
                idx4 = tid + 256; r = idx4 >> 2; c4 = (idx4 & 3) << 2;
                As[wb][r][c4 + 0] = rtf(pa1.x); As[wb][r][c4 + 1] = rtf(pa1.y);
                As[wb][r][c4 + 2] = rtf(pa1.z); As[wb][r][c4 + 3] = rtf(pa1.w);
            }
            if (!transB) {
                int idx4 = tid;
                int r = idx4 >> 2, c4 = (idx4 & 3) << 2;
                Bs[wb][r][c4 + 0] = rtf(pb0.x); Bs[wb][r][c4 + 1] = rtf(pb0.y);
                Bs[wb][r][c4 + 2] = rtf(pb0.z); Bs[wb][r][c4 + 3] = rtf(pb0.w);
                idx4 = tid + 256; r = idx4 >> 2; c4 = (idx4 & 3) << 2;
                Bs[wb][r][c4 + 0] = rtf(pb1.x); Bs[wb][r][c4 + 1] = rtf(pb1.y);
                Bs[wb][r][c4 + 2] = rtf(pb1.z); Bs[wb][r][c4 + 3] = rtf(pb1.w);
            } else {
#pragma unroll
                for (int i = 0; i < 8; i++) {
                    int idx = tid + i * 256;
                    int r = idx & 127, c = idx >> 7;
                    Bs[wb][r][c] = rtf(pbt[i]);
                }
            }
        }
        __syncthreads();
        buf ^= 1;
    }

    // ---- epilogue ----
#pragma unroll
    for (int mi = 0; mi < 2; mi++) {
#pragma unroll
        for (int nj = 0; nj < 8; nj++) {
#pragma unroll
            for (int hrow = 0; hrow < 2; hrow++) {
                int row = bm0 + wm * 32 + mi * 16 + gid + hrow * 8;
                int col = bn0 + wn * 64 + nj * 8 + tig * 2;
                float v0 = acc[mi][nj][hrow * 2 + 0];
                float v1 = acc[mi][nj][hrow * 2 + 1];
                if (mode == 0) {
                    size_t o = (size_t)row * N + col;
                    out[o]     = v0 + bias0[col]     + bias1[col];
                    out[o + 1] = v1 + bias0[col + 1] + bias1[col + 1];
                } else if (mode == 2) {
                    int bb = row & 31, tt = row >> 5;
                    size_t o = (size_t)bb * T_ * V_ + (size_t)tt * V_ + col;
                    out[o]     = v0 + bias0[col];
                    out[o + 1] = v1 + bias0[col + 1];
                } else {
                    size_t o = (size_t)row * N + col;
                    out[o] = v0; out[o + 1] = v1;
                }
            }
        }
    }
}

// =======================================================================
// Small-M GEMM body (M=32 rows): out partial z = A[32,1024] @ B[N=4096,K]^T
// chunk of K (Kchunk = 1024/SPLITK = 128). BM=32, BN=64, BK=32, 128 threads.
// =======================================================================
__device__ __forceinline__ void small_gemm_body(
    const float* __restrict__ A, const float* __restrict__ Bw, int ldb,
    float* __restrict__ out, int nblk, int z)
{
    __shared__ float As[32][33];
    __shared__ float Bs[64][33];
    const int tid  = threadIdx.x;
    const int warp = tid >> 5;
    const int lane = tid & 31;
    const int gid  = lane >> 2;
    const int tig  = lane & 3;
    const int bn0  = nblk * 64;

    float acc[2][2][4];
#pragma unroll
    for (int i = 0; i < 2; i++)
#pragma unroll
        for (int j = 0; j < 2; j++)
#pragma unroll
            for (int q = 0; q < 4; q++) acc[i][j][q] = 0.f;

    for (int kc = 0; kc < 128; kc += 32) {
        const int k0 = z * 128 + kc;
#pragma unroll
        for (int i = 0; i < 2; i++) {
            int idx4 = tid + i * 128;
            int r = idx4 >> 3, c4 = (idx4 & 7) << 2;
            float4 v = *reinterpret_cast<const float4*>(A + (size_t)r * H_ + k0 + c4);
            As[r][c4 + 0] = rtf(v.x); As[r][c4 + 1] = rtf(v.y);
            As[r][c4 + 2] = rtf(v.z); As[r][c4 + 3] = rtf(v.w);
        }
#pragma unroll
        for (int i = 0; i < 4; i++) {
            int idx4 = tid + i * 128;
            int r = idx4 >> 3, c4 = (idx4 & 7) << 2;
            float4 v = *reinterpret_cast<const float4*>(Bw + (size_t)(bn0 + r) * ldb + k0 + c4);
            Bs[r][c4 + 0] = rtf(v.x); Bs[r][c4 + 1] = rtf(v.y);
            Bs[r][c4 + 2] = rtf(v.z); Bs[r][c4 + 3] = rtf(v.w);
        }
        __syncthreads();

        const int wn = warp * 16;
#pragma unroll
        for (int k8 = 0; k8 < 4; k8++) {
            const int kk = k8 * 8;
            unsigned a[2][4], b[2][2];
#pragma unroll
            for (int mi = 0; mi < 2; mi++) {
                int mr = mi * 16 + gid;
                a[mi][0] = __float_as_uint(As[mr][kk + tig]);
                a[mi][1] = __float_as_uint(As[mr + 8][kk + tig]);
                a[mi][2] = __float_as_uint(As[mr][kk + tig + 4]);
                a[mi][3] = __float_as_uint(As[mr + 8][kk + tig + 4]);
            }
#pragma unroll
            for (int nj = 0; nj < 2; nj++) {
                int nr = wn + nj * 8 + gid;
                b[nj][0] = __float_as_uint(Bs[nr][kk + tig]);
                b[nj][1] = __float_as_uint(Bs[nr][kk + tig + 4]);
            }
#pragma unroll
            for (int mi = 0; mi < 2; mi++)
#pragma unroll
                for (int nj = 0; nj < 2; nj++)
                    mma_tf32(acc[mi][nj], a[mi], b[nj]);
        }
        __syncthreads();
    }

    const int wn = warp * 16;
#pragma unroll
    for (int mi = 0; mi < 2; mi++) {
#pragma unroll
        for (int nj = 0; nj < 2; nj++) {
#pragma unroll
            for (int hrow = 0; hrow < 2; hrow++) {
                int row = mi * 16 + gid + hrow * 8;
                int cg  = bn0 + wn + nj * 8 + tig * 2;
                size_t o = (size_t)z * B_ * G4 + (size_t)row * G4 + cg;
                out[o]     = acc[mi][nj][hrow * 2 + 0];
                out[o + 1] = acc[mi][nj][hrow * 2 + 1];
            }
        }
    }
}

// ---------------- setup kernels ----------------
__global__ void zero_hc() {
    int i = blockIdx.x * 256 + threadIdx.x;
    g_h[i] = 0.f; g_c[i] = 0.f;
}

__global__ void gather_emb(const int* __restrict__ captions, const float* __restrict__ table) {
    int m = blockIdx.x;               // m = t*B + b
    int b = m & 31, t = m >> 5;
    int tok = captions[b * T_ + t];
    const float4* src = reinterpret_cast<const float4*>(table + (size_t)tok * H_);
    float4* dst = reinterpret_cast<float4*>(g_Emb + (size_t)m * H_);
    dst[threadIdx.x] = src[threadIdx.x];
}

// ---------------- stage 1: qg GEMM (h @ W_hh^T) fused with scores (h . P) ----------------
// blocks [0,512): qg split-K GEMM.  blocks [512,736): scores, 28 s each.
__global__ void __launch_bounds__(128) stage1_kernel(const float* __restrict__ Whh) {
    const int bx = blockIdx.x;
    const int tid = threadIdx.x;
    __shared__ float hsh[H_];

    if (bx < 512) {
        small_gemm_body(g_h, Whh, H_, g_qg, bx & 63, bx >> 6);
        return;
    }
    const int ai = bx - 512;
    const int b = ai / 7, sc = ai % 7;
    for (int i = tid; i < H_; i += 128) hsh[i] = g_h[b * H_ + i];
    __syncthreads();

    const int warp = tid >> 5, lane = tid & 31;
#pragma unroll
    for (int i = 0; i < 7; i++) {
        int s = sc * 28 + i * 4 + warp;
        const float* row = g_P + ((size_t)b * S_ + s) * H_;
        float a = 0.f;
#pragma unroll 8
        for (int k = lane; k < H_; k += 32) a += hsh[k] * row[k];
#pragma unroll
        for (int o = 16; o; o >>= 1) a += __shfl_xor_sync(0xffffffffu, a, o);
        if (lane == 0) g_scores[b * S_ + s] = a;
    }
}

// ---------------- stage 2: softmax + ctx ----------------
__global__ void __launch_bounds__(256) stage2_kernel(const float* __restrict__ memory) {
    const int b = blockIdx.x >> 2, hc = blockIdx.x & 3;
    const int tid = threadIdx.x;
    __shared__ float sc[S_];
    __shared__ float red[256];

    float v = (tid < S_) ? g_scores[b * S_ + tid] : -3.4e38f;
    red[tid] = v; __syncthreads();
    for (int o = 128; o; o >>= 1) { if (tid < o) red[tid] = fmaxf(red[tid], red[tid + o]); __syncthreads(); }
    float mx = red[0]; __syncthreads();
    float e = (tid < S_) ? expf(v - mx) : 0.f;
    red[tid] = e; __syncthreads();
    for (int o = 128; o; o >>= 1) { if (tid < o) red[tid] += red[tid + o]; __syncthreads(); }
    float inv = 1.f / red[0];
    if (tid < S_) sc[tid] = e * inv;
    __syncthreads();

    const float* mb = memory + (size_t)b * S_ * H_ + hc * 256 + tid;
    float acc = 0.f;
#pragma unroll 4
    for (int s = 0; s < S_; s++) acc += sc[s] * mb[(size_t)s * H_];
    g_ctx[b * H_ + hc * 256 + tid] = acc;
}

// ---------------- stage 3: gc GEMM (ctx @ W_ihc^T) ----------------
__global__ void __launch_bounds__(128) stage3_kernel(const float* __restrict__ Wih) {
    small_gemm_body(g_ctx, Wih + H_, 2 * H_, g_gc, blockIdx.x & 63, blockIdx.x >> 6);
}

// ---------------- stage 4: LSTM cell ----------------
__global__ void __launch_bounds__(256) cell_kernel(int t) {
    int idx = blockIdx.x * 256 + threadIdx.x;   // b*1024 + j
    int b = idx >> 10, j = idx & 1023;
    const float* eg = g_EG + (size_t)(t * B_ + b) * G4;
    float gate[4];
#pragma unroll
    for (int gi = 0; gi < 4; gi++) {
        int n = j + gi * H_;
        float v = eg[n];
#pragma unroll
        for (int z = 0; z < SPLITK; z++) {
            v += g_gc[((size_t)z * B_ + b) * G4 + n];
            v += g_qg[((size_t)z * B_ + b) * G4 + n];
        }
        gate[gi] = v;
    }
    float ig = 1.f / (1.f + expf(-gate[0]));
    float fg = 1.f / (1.f + expf(-gate[1]));
    float gg = tanhf(gate[2]);
    float og = 1.f / (1.f + expf(-gate[3]));
    float c = fg * g_c[idx] + ig * gg;
    float h = og * tanhf(c);
    g_c[idx] = c;
    g_h[idx] = h;
    g_hall[(size_t)(t * B_ + b) * H_ + j] = h;
}

__global__ void final_copy(float* __restrict__ out, int out_size) {
    int i = blockIdx.x * 256 + threadIdx.x;
    size_t base = (size_t)B_ * T_ * V_;
    if ((size_t)out_size >= base + 2u * B_ * H_) {
        out[base + i]         = g_h[i];
        out[base + 32768 + i] = g_c[i];
    }
}

// ---------------- launch ----------------
extern "C" void kernel_launch(void* const* d_in, const int* in_sizes, int n_in,
                              void* d_out, int out_size) {
    const float* memory    = (const float*)d_in[0];
    const int*   captions  = (const int*)  d_in[1];
    const float* emb_table = (const float*)d_in[2];
    const float* attn_W    = (const float*)d_in[3];
    const float* W_ih      = (const float*)d_in[4];
    const float* W_hh      = (const float*)d_in[5];
    const float* b_ih      = (const float*)d_in[6];
    const float* b_hh      = (const float*)d_in[7];
    const float* W_out     = (const float*)d_in[8];
    const float* b_out     = (const float*)d_in[9];
    float* out = (float*)d_out;

    float *pEmb, *pEG, *pP, *phall;
    cudaGetSymbolAddress((void**)&pEmb,  g_Emb);
    cudaGetSymbolAddress((void**)&pEG,   g_EG);
    cudaGetSymbolAddress((void**)&pP,    g_P);
    cudaGetSymbolAddress((void**)&phall, g_hall);

    zero_hc<<<128, 256>>>();
    gather_emb<<<MROWS, 256>>>(captions, emb_table);

    // P = memory @ attn_W  (transB: attn_W is [K=H, N=H] effective)
    gemm_big<<<dim3(H_ / TN, (B_ * S_) / TM), 256>>>(
        memory, H_, attn_W, H_, 1, pP, B_ * S_, H_, nullptr, nullptr, 3);

    // EG = Emb @ W_ih[:, :H]^T + b_ih + b_hh
    gemm_big<<<dim3(G4 / TN, MROWS / TM), 256>>>(
        pEmb, H_, W_ih, 2 * H_, 0, pEG, MROWS, G4, b_ih, b_hh, 0);

    for (int t = 0; t < T_; t++) {
        stage1_kernel<<<512 + B_ * 7, 128>>>(W_hh);
        stage2_kernel<<<B_ * 4, 256>>>(memory);
        stage3_kernel<<<512, 128>>>(W_ih);
        cell_kernel<<<128, 256>>>(t);
    }

    // logits = h_all @ W_out^T + b_out, scattered to [B,T,V]; swizzled 1D grid
    gemm_big<<<(V_ / TN) * (MROWS / TM), 256>>>(
        phall, H_, W_out, H_, 0, out, MROWS, V_, b_out, nullptr, 2);

    final_copy<<<128, 256>>>(out, out_size);
}